// round 2
// baseline (speedup 1.0000x reference)
#include <cuda_runtime.h>
#include <cstdint>
#include <math.h>

// Problem constants
#define B   64
#define M   1024
#define W   64
#define R   4
#define D   512
#define IF  471   // r*w + 3*w + 5*r + 3
#define I0  256   // r*w

// ---------------- scratch (device globals; no allocation allowed) ----------------
__device__ float g_iface[B * IF];
__device__ __align__(16) float g_keys[B * R * W];
__device__ float g_kstr[B * R];     // softplus(1+relu(strength))
__device__ float g_knorm[B * R];
__device__ __align__(16) float g_wkey[B * W];
__device__ float g_wknorm[B];
__device__ float g_ws[B];           // softplus(1+relu(write strength))
__device__ __align__(16) float g_erase[B * W];
__device__ __align__(16) float g_wvec[B * W];
__device__ float g_ag[B], g_wg[B];
__device__ float g_rm[B * R * 3];
__device__ float g_usage[B * M];
__device__ float g_wc[B * M];
__device__ float g_allocw[B * M];
__device__ float g_ww[B * M];
__device__ float g_cw[B * R * M];
__device__ float g_fw[B * R * M];
__device__ float g_bw[B * R * M];
__device__ __align__(16) float g_newmem[B * M * W];

// ---------------- helpers ----------------
__device__ __forceinline__ float sigmoidf_(float x) { return 1.0f / (1.0f + expf(-x)); }
__device__ __forceinline__ float softplusf_(float x) { return (x > 20.0f) ? x : log1pf(expf(x)); }

__device__ __forceinline__ float warpMax_(float v) {
#pragma unroll
    for (int o = 16; o; o >>= 1) v = fmaxf(v, __shfl_xor_sync(0xffffffffu, v, o));
    return v;
}
__device__ __forceinline__ float warpSum_(float v) {
#pragma unroll
    for (int o = 16; o; o >>= 1) v += __shfl_xor_sync(0xffffffffu, v, o);
    return v;
}
// blockDim.x == 1024 (32 warps)
__device__ __forceinline__ float blockMax_(float v, float* sh) {
    v = warpMax_(v);
    if ((threadIdx.x & 31) == 0) sh[threadIdx.x >> 5] = v;
    __syncthreads();
    float r = sh[threadIdx.x & 31];
    r = warpMax_(r);
    __syncthreads();
    return r;
}
__device__ __forceinline__ float blockSum_(float v, float* sh) {
    v = warpSum_(v);
    if ((threadIdx.x & 31) == 0) sh[threadIdx.x >> 5] = v;
    __syncthreads();
    float r = sh[threadIdx.x & 31];
    r = warpSum_(r);
    __syncthreads();
    return r;
}

// ---------------- K1: iface = xi @ W + bW ----------------
__global__ __launch_bounds__(512) void k_iface(const float* __restrict__ xi,
                                               const float* __restrict__ Wm,
                                               const float* __restrict__ bW) {
    int b = blockIdx.x, j = threadIdx.x;
    __shared__ float xs[D];
    xs[j] = xi[b * D + j];
    __syncthreads();
    if (j < IF) {
        float acc = bW[j];
#pragma unroll 8
        for (int i = 0; i < D; i++) acc = fmaf(xs[i], Wm[i * IF + j], acc);
        g_iface[b * IF + j] = acc;
    }
}

// ---------------- K2: parse iface + usage ----------------
__global__ __launch_bounds__(512) void k_prep(const float* __restrict__ read_weights,
                                              const float* __restrict__ write_weights,
                                              const float* __restrict__ usage_vector) {
    int b = blockIdx.x, t = threadIdx.x;
    const float* f = g_iface + b * IF;

    if (t < 256) g_keys[b * 256 + t] = f[t];
    if (t >= 256 && t < 320) { int i = t - 256; g_wkey[b * W + i] = f[260 + i]; }
    if (t >= 320 && t < 384) { int i = t - 320; g_erase[b * W + i] = sigmoidf_(f[325 + i]); }
    if (t >= 384 && t < 448) { int i = t - 384; g_wvec[b * W + i] = f[389 + i]; }
    if (t < 4) {
        float x = f[256 + t];
        g_kstr[b * 4 + t] = softplusf_(1.0f + fmaxf(x, 0.0f));
        float s = 0.0f;
        for (int i = 0; i < W; i++) { float v = f[t * W + i]; s = fmaf(v, v, s); }
        g_knorm[b * 4 + t] = sqrtf(s);
    }
    if (t == 4) {
        float x = f[324];
        g_ws[b] = softplusf_(1.0f + fmaxf(x, 0.0f));
        float s = 0.0f;
        for (int i = 0; i < W; i++) { float v = f[260 + i]; s = fmaf(v, v, s); }
        g_wknorm[b] = sqrtf(s);
    }
    if (t == 5) g_ag[b] = sigmoidf_(f[457]);
    if (t == 6) g_wg[b] = sigmoidf_(f[458]);
    if (t >= 8 && t < 11) {  // read_modes: softmax over r axis, per mode j
        int j = t - 8;
        float v[4], mx = -1e30f;
        for (int rr = 0; rr < 4; rr++) { v[rr] = f[458 + rr * 3 + j]; mx = fmaxf(mx, v[rr]); }
        float s = 0.0f;
        for (int rr = 0; rr < 4; rr++) { v[rr] = expf(v[rr] - mx); s += v[rr]; }
        for (int rr = 0; rr < 4; rr++) g_rm[b * 12 + rr * 3 + j] = v[rr] / s;
    }

    float fg[4];
#pragma unroll
    for (int rr = 0; rr < 4; rr++) fg[rr] = sigmoidf_(f[453 + rr]);
    for (int m = t; m < M; m += 512) {
        float uv = usage_vector[b * M + m];
        float wwo = write_weights[b * M + m];
        float u = uv + (1.0f - uv) * wwo;  // k=1: 1 - prod(1-ww) == ww
        float psi = 1.0f;
#pragma unroll
        for (int rr = 0; rr < 4; rr++)
            psi *= (1.0f - fg[rr] * read_weights[(b * 4 + rr) * M + m]);
        g_usage[b * M + m] = u * psi;
    }
}

// ---------------- K3: write content weighting (softmax over m) ----------------
__global__ __launch_bounds__(1024) void k_write_content(const float* __restrict__ memory) {
    int b = blockIdx.x, t = threadIdx.x;
    __shared__ float4 key_s[16];
    __shared__ float dvals[M];
    __shared__ float red[32];
    if (t < 16) key_s[t] = ((const float4*)(g_wkey + b * W))[t];
    __syncthreads();
    float knorm = g_wknorm[b] + 1e-6f;
    float s = g_ws[b];
    int row = t >> 4, lane = t & 15;
    const float4* mem4 = (const float4*)(memory + (size_t)b * M * W);
    for (int g = 0; g < 16; g++) {
        int m = g * 64 + row;
        float4 v = mem4[m * 16 + lane];
        float4 k = key_s[lane];
        float dot = v.x * k.x + v.y * k.y + v.z * k.z + v.w * k.w;
        float ns  = v.x * v.x + v.y * v.y + v.z * v.z + v.w * v.w;
#pragma unroll
        for (int o = 8; o; o >>= 1) {
            dot += __shfl_xor_sync(0xffffffffu, dot, o);
            ns  += __shfl_xor_sync(0xffffffffu, ns, o);
        }
        if (lane == 0) dvals[m] = dot * s / ((sqrtf(ns) + 1e-6f) * knorm);
    }
    __syncthreads();
    float x = dvals[t];
    float mx = blockMax_(x, red);
    float e = expf(x - mx);
    float sm = blockSum_(e, red);
    g_wc[b * M + t] = e / sm;
}

// ---------------- K4: allocation (stable argsort + inclusive cumprod) ----------------
__global__ __launch_bounds__(1024) void k_allocation() {
    int b = blockIdx.x, t = threadIdx.x;
    __shared__ unsigned long long keys[M];
    __shared__ float pvals[M];
    float u = 1e-6f + (1.0f - 1e-6f) * g_usage[b * M + t];
    keys[t] = ((unsigned long long)__float_as_uint(u) << 32) | (unsigned)t; // u>0 -> bits monotone; idx = stable tiebreak
    __syncthreads();
    for (int k = 2; k <= M; k <<= 1) {
        for (int j = k >> 1; j > 0; j >>= 1) {
            int ixj = t ^ j;
            if (ixj > t) {
                unsigned long long a = keys[t], c = keys[ixj];
                bool asc = ((t & k) == 0);
                if ((a > c) == asc) { keys[t] = c; keys[ixj] = a; }
            }
            __syncthreads();
        }
    }
    float su = __uint_as_float((unsigned)(keys[t] >> 32));
    pvals[t] = su;
    __syncthreads();
    for (int off = 1; off < M; off <<= 1) {   // inclusive product scan
        float v = (t >= off) ? pvals[t - off] : 1.0f;
        __syncthreads();
        pvals[t] *= v;
        __syncthreads();
    }
    int idx = (int)(keys[t] & 0xffffffffULL);
    g_allocw[b * M + idx] = (1.0f - su) * pvals[t];
}

// ---------------- K5: zero fw/bw accumulators ----------------
__global__ __launch_bounds__(1024) void k_zero() {
    int i = blockIdx.x * 1024 + threadIdx.x;
    if (i < B * R * M) { g_fw[i] = 0.0f; g_bw[i] = 0.0f; }
}

// ---------------- K6: fused ww + memory update + read content softmax ----------------
__global__ __launch_bounds__(1024) void k_memupdate_content(const float* __restrict__ memory) {
    int b = blockIdx.x, t = threadIdx.x;
    __shared__ float ww_s[M];
    __shared__ float4 rk_s[4 * 16];
    __shared__ float4 e_s[16], wv_s[16];
    __shared__ float d_s[4][M];
    __shared__ float red[32];

    float ag = g_ag[b], wg = g_wg[b];
    {
        float a = g_allocw[b * M + t];
        float wcv = g_wc[b * M + t];
        float ww = wg * (ag * a + (1.0f - ag) * wcv);
        ww_s[t] = ww;
        g_ww[b * M + t] = ww;
    }
    if (t < 64) rk_s[t] = ((const float4*)(g_keys + b * 256))[t];
    if (t >= 64 && t < 80) e_s[t - 64] = ((const float4*)(g_erase + b * W))[t - 64];
    if (t >= 80 && t < 96) wv_s[t - 80] = ((const float4*)(g_wvec + b * W))[t - 80];
    float kn[4], ks[4];
#pragma unroll
    for (int rr = 0; rr < 4; rr++) { kn[rr] = g_knorm[b * 4 + rr] + 1e-6f; ks[rr] = g_kstr[b * 4 + rr]; }
    __syncthreads();

    int row = t >> 4, lane = t & 15;
    const float4* mem4 = (const float4*)(memory + (size_t)b * M * W);
    float4* nm4 = (float4*)(g_newmem + (size_t)b * M * W);
    for (int g = 0; g < 16; g++) {
        int m = g * 64 + row;
        float wwm = ww_s[m];
        float4 v = mem4[m * 16 + lane];
        float4 e = e_s[lane], wv = wv_s[lane];
        float4 nm;
        nm.x = fmaf(v.x, fmaf(-wwm, e.x, 1.0f), wwm * wv.x);
        nm.y = fmaf(v.y, fmaf(-wwm, e.y, 1.0f), wwm * wv.y);
        nm.z = fmaf(v.z, fmaf(-wwm, e.z, 1.0f), wwm * wv.z);
        nm.w = fmaf(v.w, fmaf(-wwm, e.w, 1.0f), wwm * wv.w);
        nm4[m * 16 + lane] = nm;
        float ns = nm.x * nm.x + nm.y * nm.y + nm.z * nm.z + nm.w * nm.w;
        float dr[4];
#pragma unroll
        for (int rr = 0; rr < 4; rr++) {
            float4 k = rk_s[rr * 16 + lane];
            dr[rr] = nm.x * k.x + nm.y * k.y + nm.z * k.z + nm.w * k.w;
        }
#pragma unroll
        for (int o = 8; o; o >>= 1) {
            ns += __shfl_xor_sync(0xffffffffu, ns, o);
#pragma unroll
            for (int rr = 0; rr < 4; rr++) dr[rr] += __shfl_xor_sync(0xffffffffu, dr[rr], o);
        }
        if (lane == 0) {
            float inv = 1.0f / (sqrtf(ns) + 1e-6f);
#pragma unroll
            for (int rr = 0; rr < 4; rr++) d_s[rr][m] = dr[rr] * ks[rr] * inv / kn[rr];
        }
    }
    __syncthreads();
#pragma unroll
    for (int rr = 0; rr < 4; rr++) {
        float x = d_s[rr][t];
        float mx = blockMax_(x, red);
        float e = expf(x - mx);
        float sm = blockSum_(e, red);
        g_cw[(b * 4 + rr) * M + t] = e / sm;
    }
}

// ---------------- K7: fused link-matrix kernel (fw/bw) ----------------
// new_link[m,n] = (m!=n) * ((1 - ww[m] - ww[n]) * L[m,n] + ww[m]*prec_old[n])
// fw[r][m] = sum_n NL[m,n]*rw_old[r][n]; bw[r][n] = sum_m NL[m,n]*rw_old[r][m]
__global__ __launch_bounds__(256) void k_link(const float* __restrict__ link,
                                              const float* __restrict__ precedence,
                                              const float* __restrict__ read_weights) {
    int mt = blockIdx.x;   // 8 tiles of 128 rows
    int b  = blockIdx.y;
    int t  = threadIdx.x;
    __shared__ __align__(16) float ww_s[M];
    __shared__ __align__(16) float pr_s[M];
    __shared__ __align__(16) float rw_s[4][M];
    __shared__ float fw_s[4][128];

    for (int i = t; i < M; i += 256) {
        ww_s[i] = g_ww[b * M + i];
        pr_s[i] = precedence[b * M + i];
    }
    for (int i = t; i < 4 * M; i += 256) ((float*)rw_s)[i] = read_weights[b * 4 * M + i];
    if (t < 512) ((float*)fw_s)[t] = 0.0f;
    __syncthreads();

    int n0 = t * 4;
    int lane = t & 31;
    float4 pn  = *(const float4*)&pr_s[n0];
    float4 wwn = *(const float4*)&ww_s[n0];
    float4 rwn[4];
#pragma unroll
    for (int rr = 0; rr < 4; rr++) rwn[rr] = *(const float4*)&rw_s[rr][n0];
    float4 bwa[4];
#pragma unroll
    for (int rr = 0; rr < 4; rr++) bwa[rr] = make_float4(0.f, 0.f, 0.f, 0.f);

    const float4* L4 = (const float4*)(link + (size_t)b * M * M);

#pragma unroll 2
    for (int mi = 0; mi < 128; mi++) {
        int m = mt * 128 + mi;
        float wwm = ww_s[m];
        float cm = 1.0f - wwm;
        float r0 = rw_s[0][m], r1 = rw_s[1][m], r2 = rw_s[2][m], r3 = rw_s[3][m];
        float4 L = L4[(size_t)m * 256 + t];
        float nl0 = fmaf(L.x, cm - wwn.x, wwm * pn.x);
        float nl1 = fmaf(L.y, cm - wwn.y, wwm * pn.y);
        float nl2 = fmaf(L.z, cm - wwn.z, wwm * pn.z);
        float nl3 = fmaf(L.w, cm - wwn.w, wwm * pn.w);
        if (n0 + 0 == m) nl0 = 0.0f;
        if (n0 + 1 == m) nl1 = 0.0f;
        if (n0 + 2 == m) nl2 = 0.0f;
        if (n0 + 3 == m) nl3 = 0.0f;

        float f0 = nl0 * rwn[0].x + nl1 * rwn[0].y + nl2 * rwn[0].z + nl3 * rwn[0].w;
        float f1 = nl0 * rwn[1].x + nl1 * rwn[1].y + nl2 * rwn[1].z + nl3 * rwn[1].w;
        float f2 = nl0 * rwn[2].x + nl1 * rwn[2].y + nl2 * rwn[2].z + nl3 * rwn[2].w;
        float f3 = nl0 * rwn[3].x + nl1 * rwn[3].y + nl2 * rwn[3].z + nl3 * rwn[3].w;

        bwa[0].x = fmaf(nl0, r0, bwa[0].x); bwa[0].y = fmaf(nl1, r0, bwa[0].y);
        bwa[0].z = fmaf(nl2, r0, bwa[0].z); bwa[0].w = fmaf(nl3, r0, bwa[0].w);
        bwa[1].x = fmaf(nl0, r1, bwa[1].x); bwa[1].y = fmaf(nl1, r1, bwa[1].y);
        bwa[1].z = fmaf(nl2, r1, bwa[1].z); bwa[1].w = fmaf(nl3, r1, bwa[1].w);
        bwa[2].x = fmaf(nl0, r2, bwa[2].x); bwa[2].y = fmaf(nl1, r2, bwa[2].y);
        bwa[2].z = fmaf(nl2, r2, bwa[2].z); bwa[2].w = fmaf(nl3, r2, bwa[2].w);
        bwa[3].x = fmaf(nl0, r3, bwa[3].x); bwa[3].y = fmaf(nl1, r3, bwa[3].y);
        bwa[3].z = fmaf(nl2, r3, bwa[3].z); bwa[3].w = fmaf(nl3, r3, bwa[3].w);

#pragma unroll
        for (int o = 16; o; o >>= 1) {
            f0 += __shfl_xor_sync(0xffffffffu, f0, o);
            f1 += __shfl_xor_sync(0xffffffffu, f1, o);
            f2 += __shfl_xor_sync(0xffffffffu, f2, o);
            f3 += __shfl_xor_sync(0xffffffffu, f3, o);
        }
        if (lane == 0) {
            atomicAdd(&fw_s[0][mi], f0);
            atomicAdd(&fw_s[1][mi], f1);
            atomicAdd(&fw_s[2][mi], f2);
            atomicAdd(&fw_s[3][mi], f3);
        }
    }
    __syncthreads();
    if (t < 512) {
        int rr = t >> 7, mi = t & 127;
        g_fw[(b * 4 + rr) * M + mt * 128 + mi] = fw_s[rr][mi];
    }
#pragma unroll
    for (int rr = 0; rr < 4; rr++) {
        float* dst = &g_bw[(b * 4 + rr) * M + n0];
        atomicAdd(dst + 0, bwa[rr].x);
        atomicAdd(dst + 1, bwa[rr].y);
        atomicAdd(dst + 2, bwa[rr].z);
        atomicAdd(dst + 3, bwa[rr].w);
    }
}

// ---------------- K8: combine modes + read vectors ----------------
__global__ __launch_bounds__(256) void k_output(float* __restrict__ out) {
    int b = blockIdx.x, t = threadIdx.x;
    __shared__ float nrw_s[4][M];
    for (int idx = t; idx < 4 * M; idx += 256) {
        int rr = idx >> 10, m = idx & 1023;
        float rm0 = g_rm[b * 12 + rr * 3 + 0];
        float rm1 = g_rm[b * 12 + rr * 3 + 1];
        float rm2 = g_rm[b * 12 + rr * 3 + 2];
        nrw_s[rr][m] = rm0 * g_bw[(b * 4 + rr) * M + m]
                     + rm1 * g_fw[(b * 4 + rr) * M + m]
                     + rm2 * g_cw[(b * 4 + rr) * M + m];
    }
    __syncthreads();
    int rr = t >> 6, wl = t & 63;
    const float* nmB = g_newmem + (size_t)b * M * W;
    float acc = 0.0f;
#pragma unroll 4
    for (int m = 0; m < M; m++) acc = fmaf(nrw_s[rr][m], nmB[m * W + wl], acc);
    out[(b * 4 + rr) * W + wl] = acc;
}

// ---------------- launch ----------------
extern "C" void kernel_launch(void* const* d_in, const int* in_sizes, int n_in,
                              void* d_out, int out_size) {
    const float* xi   = (const float*)d_in[0];
    const float* Wm   = (const float*)d_in[1];
    const float* bW   = (const float*)d_in[2];
    const float* mem  = (const float*)d_in[3];
    const float* link = (const float*)d_in[4];
    const float* prec = (const float*)d_in[5];
    const float* rw   = (const float*)d_in[6];
    const float* wwo  = (const float*)d_in[7];
    const float* uv   = (const float*)d_in[8];
    float* out = (float*)d_out;

    k_iface<<<B, 512>>>(xi, Wm, bW);
    k_prep<<<B, 512>>>(rw, wwo, uv);
    k_write_content<<<B, 1024>>>(mem);
    k_allocation<<<B, 1024>>>();
    k_zero<<<(B * R * M + 1023) / 1024, 1024>>>();
    k_memupdate_content<<<B, 1024>>>(mem);
    k_link<<<dim3(8, B), 256>>>(link, prec, rw);
    k_output<<<B, 256>>>(out);
}